// round 3
// baseline (speedup 1.0000x reference)
#include <cuda_runtime.h>

#define LSEQ 32768
#define T 14
#define EMB 300
#define EMB4 75
#define CHUNKS 256
#define CB 128            // chunk length (CHUNKS*CB == LSEQ)
#define PITCH 16          // global matrix row pitch (floats)
#define SPITCH 17         // smem matrix row pitch (floats, conflict-free)
#define START_TAG 12
#define STOP_TAG 13
#define NEGV (-10000.0f)
#define NINF (-1e30f)

// ---------------- scratch (static device globals; no allocation) -------------
__device__ float g_feats[LSEQ * T];                 // emission scores
__device__ float g_Cf[CHUNKS * T * PITCH];          // forward (log-semiring) chunk mats
__device__ float g_Cv[CHUNKS * T * PITCH];          // viterbi (max-plus) chunk mats
__device__ float g_G16[16 * T * PITCH];             // stage-1 combined forward mats
__device__ float g_vstart[CHUNKS * PITCH];          // viterbi vector at each chunk start
__device__ float g_goldpart[64];                    // gold-score partial sums
__device__ float g_fs[1];                           // forward score
__device__ float g_gold[1];
__device__ int   g_best_last[1];
__device__ unsigned char g_bp[LSEQ * T];            // backpointers
__device__ unsigned char g_F[CHUNKS * T];           // per-chunk backtrace maps
__device__ int   g_carry[CHUNKS];                   // carry-in tag per chunk

// ---------------- K1: feats[l][t] = emb[sentence[l]] . W[t] ------------------
__global__ void k_feats(const int* __restrict__ sent,
                        const float* __restrict__ emb,
                        const float* __restrict__ W) {
    __shared__ __align__(16) float Ws[T * EMB];
    for (int i = threadIdx.x; i < T * EMB; i += blockDim.x) Ws[i] = W[i];
    __syncthreads();
    int l = blockIdx.x * blockDim.x + threadIdx.x;
    if (l >= LSEQ) return;
    const float4* e4 = (const float4*)(emb + (size_t)sent[l] * EMB);
    float acc[T];
#pragma unroll
    for (int t = 0; t < T; t++) acc[t] = 0.0f;
    for (int k = 0; k < EMB4; k++) {
        float4 ev = e4[k];
#pragma unroll
        for (int t = 0; t < T; t++) {
            float4 wv = *(const float4*)(Ws + t * EMB + 4 * k);   // broadcast read
            float a = acc[t];
            a = fmaf(ev.x, wv.x, a);
            a = fmaf(ev.y, wv.y, a);
            a = fmaf(ev.z, wv.z, a);
            a = fmaf(ev.w, wv.w, a);
            acc[t] = a;
        }
    }
#pragma unroll
    for (int t = 0; t < T; t++) g_feats[l * T + t] = acc[t];
}

// ---------------- K1b: gold score partials (deterministic tree) --------------
__global__ void k_gold(const int* __restrict__ tags,
                       const float* __restrict__ trans) {
    __shared__ float red[256];
    float s = 0.0f;
    for (int l = blockIdx.x * blockDim.x + threadIdx.x; l < LSEQ;
         l += gridDim.x * blockDim.x) {
        int t = tags[l];
        int prev = (l == 0) ? START_TAG : tags[l - 1];
        float v = trans[t * T + prev] + g_feats[l * T + t];
        if (l == LSEQ - 1) v += trans[STOP_TAG * T + t];
        s += v;
    }
    red[threadIdx.x] = s;
    __syncthreads();
    for (int off = 128; off; off >>= 1) {
        if (threadIdx.x < off) red[threadIdx.x] += red[threadIdx.x + off];
        __syncthreads();
    }
    if (threadIdx.x == 0) g_goldpart[blockIdx.x] = red[0];
}

// ---------------- K2: per-chunk semiring matrices (fwd & viterbi) ------------
// blocks [0,CHUNKS) : forward log-semiring;  [CHUNKS,2*CHUNKS) : max-plus
__global__ void k_chunks(const float* __restrict__ trans) {
    __shared__ float Mbuf[2][T * SPITCH];
    __shared__ float feat_s[CB * T];
    int fwd = (blockIdx.x < CHUNKS);
    int chunk = fwd ? blockIdx.x : (blockIdx.x - CHUNKS);
    int tid = threadIdx.x;                     // blockDim == 196
    for (int i = tid; i < CB * T; i += 196)
        feat_s[i] = g_feats[chunk * CB * T + i];
    int n = tid % T, c = tid / T;
    float tr[T];
#pragma unroll
    for (int p = 0; p < T; p++) tr[p] = trans[n * T + p];
    Mbuf[0][n * SPITCH + c] = (n == c) ? 0.0f : NINF;
    __syncthreads();
    int b = 0;
    for (int l = 0; l < CB; l++) {
        const float* Mo = Mbuf[b];
        float a[T];
#pragma unroll
        for (int p = 0; p < T; p++) a[p] = Mo[p * SPITCH + c] + tr[p];
        float m = a[0];
#pragma unroll
        for (int p = 1; p < T; p++) m = fmaxf(m, a[p]);
        float r;
        if (fwd) {
            float s = 0.0f;
#pragma unroll
            for (int p = 0; p < T; p++) s += __expf(a[p] - m);
            r = m + __logf(s);
        } else {
            r = m;
        }
        Mbuf[b ^ 1][n * SPITCH + c] = r + feat_s[l * T + n];
        __syncthreads();
        b ^= 1;
    }
    float* dst = fwd ? g_Cf : g_Cv;
    dst[chunk * T * PITCH + n * PITCH + c] = Mbuf[b][n * SPITCH + c];
}

// ---------------- K3: combine 16 forward chunk mats per block ----------------
__global__ void k_comb16(void) {
    __shared__ float A[T * SPITCH];
    __shared__ float R[2][T * SPITCH];
    int tid = threadIdx.x;                     // 196
    int n = tid / T, c = tid % T;
    R[0][n * SPITCH + c] = (n == c) ? 0.0f : NINF;
    int b = 0;
    for (int k = 0; k < 16; k++) {
        A[n * SPITCH + c] = g_Cf[(blockIdx.x * 16 + k) * T * PITCH + n * PITCH + c];
        __syncthreads();
        float a[T];
#pragma unroll
        for (int p = 0; p < T; p++) a[p] = A[n * SPITCH + p] + R[b][p * SPITCH + c];
        float m = a[0];
#pragma unroll
        for (int p = 1; p < T; p++) m = fmaxf(m, a[p]);
        float s = 0.0f;
#pragma unroll
        for (int p = 0; p < T; p++) s += __expf(a[p] - m);
        R[b ^ 1][n * SPITCH + c] = m + __logf(s);
        __syncthreads();
        b ^= 1;
    }
    g_G16[blockIdx.x * T * PITCH + n * PITCH + c] = R[b][n * SPITCH + c];
}

// ---------------- K4: final forward combine + gold + viterbi prefix scan -----
__global__ void k_small(const float* __restrict__ trans, float* __restrict__ out) {
    __shared__ float A[T * SPITCH];
    __shared__ float R[2][T * SPITCH];
    __shared__ float fsh[1], goldsh[1];
    int tid = threadIdx.x;                     // blockDim == 256
    int active = (tid < 196);
    int n = tid / T, c = tid % T;
    if (active) R[0][n * SPITCH + c] = (n == c) ? 0.0f : NINF;
    int b = 0;
    for (int k = 0; k < 16; k++) {
        if (active) A[n * SPITCH + c] = g_G16[k * T * PITCH + n * PITCH + c];
        __syncthreads();
        if (active) {
            float a[T];
#pragma unroll
            for (int p = 0; p < T; p++) a[p] = A[n * SPITCH + p] + R[b][p * SPITCH + c];
            float m = a[0];
#pragma unroll
            for (int p = 1; p < T; p++) m = fmaxf(m, a[p]);
            float s = 0.0f;
#pragma unroll
            for (int p = 0; p < T; p++) s += __expf(a[p] - m);
            R[b ^ 1][n * SPITCH + c] = m + __logf(s);
        }
        __syncthreads();
        b ^= 1;
    }
    if (tid == 0) {
        // fv_L[n] = LSE_p( P[n][p] + init[p] ) ; forward = LSE_n( fv_L + trans[STOP] )
        float fv[T];
#pragma unroll
        for (int nn = 0; nn < T; nn++) {
            float m = -3e38f;
#pragma unroll
            for (int p = 0; p < T; p++) {
                float ip = (p == START_TAG) ? 0.0f : NEGV;
                m = fmaxf(m, R[b][nn * SPITCH + p] + ip);
            }
            float s = 0.0f;
#pragma unroll
            for (int p = 0; p < T; p++) {
                float ip = (p == START_TAG) ? 0.0f : NEGV;
                s += __expf(R[b][nn * SPITCH + p] + ip - m);
            }
            fv[nn] = m + __logf(s);
        }
        float m = -3e38f;
#pragma unroll
        for (int nn = 0; nn < T; nn++) m = fmaxf(m, fv[nn] + trans[STOP_TAG * T + nn]);
        float s = 0.0f;
#pragma unroll
        for (int nn = 0; nn < T; nn++) s += __expf(fv[nn] + trans[STOP_TAG * T + nn] - m);
        fsh[0] = m + __logf(s);
        float g = 0.0f;
        for (int i = 0; i < 64; i++) g += g_goldpart[i];
        goldsh[0] = g;
        g_fs[0] = fsh[0];
        g_gold[0] = g;
        out[0] = fsh[0] - g;                   // nll
    }
    __syncthreads();
    // viterbi prefix scan across chunk matrices (warp 0, lanes 0..13)
    if (tid < T) {
        int lane = tid;
        float v = (lane == START_TAG) ? 0.0f : NEGV;
        float c0r[T], c1r[T], nx[T];
#pragma unroll
        for (int p = 0; p < T; p++) c0r[p] = g_Cv[lane * PITCH + p];
#pragma unroll
        for (int p = 0; p < T; p++) c1r[p] = g_Cv[T * PITCH + lane * PITCH + p];
#pragma unroll
        for (int p = 0; p < T; p++) nx[p] = NINF;
        for (int i = 0; i < CHUNKS; i++) {
            g_vstart[i * PITCH + lane] = v;
            if (i + 2 < CHUNKS) {
#pragma unroll
                for (int p = 0; p < T; p++)
                    nx[p] = g_Cv[(i + 2) * T * PITCH + lane * PITCH + p];
            }
            float best = NINF;
#pragma unroll
            for (int p = 0; p < T; p++) {
                float vp = __shfl_sync(0x3FFFu, v, p);
                best = fmaxf(best, vp + c0r[p]);
            }
            v = best;
#pragma unroll
            for (int p = 0; p < T; p++) { c0r[p] = c1r[p]; c1r[p] = nx[p]; }
        }
    }
}

// ---------------- K5: per-chunk viterbi walk -> backpointers + chunk map -----
__global__ void k_bp(const float* __restrict__ trans, float* __restrict__ out) {
    __shared__ float feat_s[CB * T];
    __shared__ unsigned char bp_s[CB * T];
    __shared__ float term_s[T];
    int chunk = blockIdx.x;
    int tid = threadIdx.x;                     // blockDim == 64
    for (int i = tid; i < CB * T; i += 64)
        feat_s[i] = g_feats[chunk * CB * T + i];
    __syncthreads();
    if (tid < T) {
        int lane = tid;
        float tr[T];
#pragma unroll
        for (int p = 0; p < T; p++) tr[p] = trans[lane * T + p];
        float fv = g_vstart[chunk * PITCH + lane];
        for (int l = 0; l < CB; l++) {
            float best = NINF;
            int arg = 0;
#pragma unroll
            for (int p = 0; p < T; p++) {
                float vp = __shfl_sync(0x3FFFu, fv, p);
                float a2 = vp + tr[p];
                if (a2 > best) { best = a2; arg = p; }   // first-max (jnp.argmax)
            }
            unsigned char ab = (unsigned char)arg;
            bp_s[l * T + lane] = ab;
            g_bp[chunk * CB * T + l * T + lane] = ab;
            fv = best + feat_s[l * T + lane];
        }
        __syncwarp(0x3FFFu);
        // chunk backtrace map F_i
        int t = lane;
        for (int l = CB - 1; l >= 0; l--) t = bp_s[l * T + t];
        g_F[chunk * T + lane] = (unsigned char)t;
        // last chunk: terminal scores, best_last, path_score (consistent w/ walk)
        if (chunk == CHUNKS - 1) {
            term_s[lane] = fv + trans[STOP_TAG * T + lane];
            __syncwarp(0x3FFFu);
            if (lane == 0) {
                float best = -3e38f;
                int arg = 0;
#pragma unroll
                for (int nn = 0; nn < T; nn++) {
                    float tv = term_s[nn];
                    if (tv > best) { best = tv; arg = nn; }
                }
                g_best_last[0] = arg;
                out[1] = best;                 // path_score
            }
        }
    }
}

// ---------------- K6: carry chain over chunk maps ----------------------------
__global__ void k_carry(void) {
    __shared__ unsigned char F_s[CHUNKS * T];
    int tid = threadIdx.x;                     // 256
    for (int i = tid; i < CHUNKS * T; i += 256) F_s[i] = g_F[i];
    __syncthreads();
    if (tid == 0) {
        int cc = g_best_last[0];
        for (int i = CHUNKS - 1; i >= 0; i--) {
            g_carry[i] = cc;
            cc = F_s[i * T + cc];
        }
    }
}

// ---------------- K7: emit path ----------------------------------------------
__global__ void k_path(float* __restrict__ out) {
    __shared__ unsigned char bp_s[CB * T];
    int chunk = blockIdx.x;
    int tid = threadIdx.x;                     // 64
    for (int i = tid; i < CB * T; i += 64)
        bp_s[i] = g_bp[chunk * CB * T + i];
    __syncthreads();
    if (tid == 0) {
        int cc = g_carry[chunk];
        for (int l = CB - 1; l >= 0; l--) {
            out[2 + chunk * CB + l] = (float)cc;
            cc = bp_s[l * T + cc];
        }
    }
}

// ---------------- launch -----------------------------------------------------
extern "C" void kernel_launch(void* const* d_in, const int* in_sizes, int n_in,
                              void* d_out, int out_size) {
    const int*   sent  = (const int*)d_in[0];
    const int*   tags  = (const int*)d_in[1];
    const float* emb   = (const float*)d_in[2];
    const float* W     = (const float*)d_in[3];
    const float* trans = (const float*)d_in[4];
    float* out = (float*)d_out;
    (void)in_sizes; (void)n_in; (void)out_size;

    k_feats<<<LSEQ / 256, 256>>>(sent, emb, W);
    k_gold<<<64, 256>>>(tags, trans);
    k_chunks<<<2 * CHUNKS, 196>>>(trans);
    k_comb16<<<16, 196>>>();
    k_small<<<1, 256>>>(trans, out);
    k_bp<<<CHUNKS, 64>>>(trans, out);
    k_carry<<<1, 256>>>();
    k_path<<<CHUNKS, 64>>>(out);
}

// round 4
// speedup vs baseline: 2.0570x; 2.0570x over previous
#include <cuda_runtime.h>

#define LSEQ 32768
#define T 14
#define EMB 300
#define CHUNKS 256
#define CB 128            // chunk length
#define SUPER 16          // supernodes
#define SCH 16            // chunks per supernode
#define START_TAG 12
#define STOP_TAG 13
#define NEGV (-10000.0f)
#define NINF (-1e30f)

// ---------------- scratch (static device globals; no allocation) -------------
__device__ float g_featsP[LSEQ * 16];          // feats padded to 16 (pads stay 0)
__device__ float g_goldpart[256];
__device__ float g_Em[CHUNKS * 224];           // fwd chunk mats, row-normalized linear
__device__ float g_m[CHUNKS * 16];             // per-row log offsets for g_Em
__device__ float g_Cv[CHUNKS * 224];           // viterbi chunk mats (log / max-plus)
__device__ float g_SEm[SUPER * 224];           // supernode fwd mats (linear, row-norm)
__device__ float g_Sm[SUPER * 16];
__device__ float g_SCv[SUPER * 224];           // supernode viterbi mats
__device__ float g_vsuper[SUPER * 16];         // viterbi vector at supernode starts
__device__ int   g_best_last[1];
__device__ unsigned char g_bp[LSEQ * T];
__device__ unsigned char g_F[CHUNKS * T];
__device__ int   g_carry[CHUNKS];

__device__ __forceinline__ void ld14(const float* p, float* u) {
    const float4* q = (const float4*)p;
    float4 a = q[0], b = q[1], c = q[2], d = q[3];
    u[0]=a.x; u[1]=a.y; u[2]=a.z; u[3]=a.w;
    u[4]=b.x; u[5]=b.y; u[6]=b.z; u[7]=b.w;
    u[8]=c.x; u[9]=c.y; u[10]=c.z; u[11]=c.w;
    u[12]=d.x; u[13]=d.y;
}
__device__ __forceinline__ float max14(const float* u) {
    float a0=fmaxf(u[0],u[1]), a1=fmaxf(u[2],u[3]), a2=fmaxf(u[4],u[5]);
    float a3=fmaxf(u[6],u[7]), a4=fmaxf(u[8],u[9]), a5=fmaxf(u[10],u[11]);
    float a6=fmaxf(u[12],u[13]);
    float b0=fmaxf(a0,a1), b1=fmaxf(a2,a3), b2=fmaxf(a4,a5);
    return fmaxf(fmaxf(b0,b1), fmaxf(b2,a6));
}

// ---------------- K1: feats + fused gold partials ----------------------------
__global__ void k_feats(const int* __restrict__ sent, const int* __restrict__ tags,
                        const float* __restrict__ emb, const float* __restrict__ W,
                        const float* __restrict__ trans) {
    __shared__ __align__(16) float Ws[T * EMB];
    __shared__ float red[128];
    for (int i = threadIdx.x; i < T * EMB; i += 128) Ws[i] = W[i];
    __syncthreads();
    int l = blockIdx.x * 128 + threadIdx.x;
    const float4* e4 = (const float4*)(emb + (size_t)sent[l] * EMB);
    float acc[T];
#pragma unroll
    for (int t = 0; t < T; t++) acc[t] = 0.0f;
    for (int k = 0; k < EMB / 4; k++) {
        float4 ev = e4[k];
#pragma unroll
        for (int t = 0; t < T; t++) {
            float4 wv = *(const float4*)(Ws + t * EMB + 4 * k);
            float a = acc[t];
            a = fmaf(ev.x, wv.x, a); a = fmaf(ev.y, wv.y, a);
            a = fmaf(ev.z, wv.z, a); a = fmaf(ev.w, wv.w, a);
            acc[t] = a;
        }
    }
#pragma unroll
    for (int t = 0; t < T; t++) g_featsP[l * 16 + t] = acc[t];
    // gold contribution for this position (predicated select, no local spill)
    int tg = tags[l];
    int prev = (l == 0) ? START_TAG : tags[l - 1];
    float emit = 0.0f;
#pragma unroll
    for (int t = 0; t < T; t++) if (t == tg) emit = acc[t];
    float gv = trans[tg * T + prev] + emit;
    if (l == LSEQ - 1) gv += trans[STOP_TAG * T + tg];
    red[threadIdx.x] = gv;
    __syncthreads();
    for (int off = 64; off; off >>= 1) {
        if (threadIdx.x < off) red[threadIdx.x] += red[threadIdx.x + off];
        __syncthreads();
    }
    if (threadIdx.x == 0) g_goldpart[blockIdx.x] = red[0];
}

// ---------------- K2: per-chunk semiring matrices ----------------------------
// blocks [0,CHUNKS): forward in LINEAR domain (1 MUFU/thread/step)
// blocks [CHUNKS,2*CHUNKS): viterbi max-plus
__global__ void k_chunks(const float* __restrict__ trans) {
    __shared__ __align__(16) float Ubuf[2][224];   // transposed: [c*16+n]
    __shared__ __align__(16) float aux[CB * 16];   // fwd: exp(feat-fmax); vit: raw feat
    __shared__ float fmaxs[CB];
    __shared__ __align__(16) float Etr_s[224];
    __shared__ __align__(16) float Msm[224];
    __shared__ float o_s[16];
    __shared__ float fsum_s;
    int fwd = (blockIdx.x < CHUNKS);
    int chunk = fwd ? blockIdx.x : blockIdx.x - CHUNKS;
    int tid = threadIdx.x;                          // 196 threads
    int n = tid % T, c = tid / T;
    {   // stage trans (fwd: exp'd; exp(-10000)=0 acts as -inf exactly)
        int nn = tid / T, pp = tid % T;
        float tv = trans[nn * T + pp];
        Etr_s[nn * 16 + pp] = fwd ? __expf(tv) : tv;
    }
    if (fwd) {
        if (tid < CB) {
            float f[16];
            ld14(g_featsP + (chunk * CB + tid) * 16, f);
            float fm = max14(f);
            fmaxs[tid] = fm;
#pragma unroll
            for (int j = 0; j < T; j++) aux[tid * 16 + j] = __expf(f[j] - fm);
        }
    } else {
        const float4* src = (const float4*)(g_featsP + chunk * CB * 16);
        float4* dst = (float4*)aux;
        for (int i = tid; i < CB * 4; i += 196) dst[i] = src[i];
    }
    Ubuf[0][c * 16 + n] = fwd ? ((n == c) ? 1.0f : 0.0f)
                              : ((n == c) ? 0.0f : NINF);
    __syncthreads();
    if (fwd && tid == 0) {
        float s = 0.0f;
        for (int l2 = 0; l2 < CB; l2++) s += fmaxs[l2];
        fsum_s = s;
    }
    float tr[T];
#pragma unroll
    for (int p = 0; p < T; p++) tr[p] = Etr_s[n * 16 + p];
    float o = 0.0f;
    int b = 0;
    if (fwd) {
        for (int l = 0; l < CB; l++) {
            float u[T];
            ld14(&Ubuf[b][c * 16], u);
            float cm = fmaxf(max14(u), 1e-35f);        // column max (lagged norm)
            float s0 = 0.0f, s1 = 0.0f;
#pragma unroll
            for (int p = 0; p < 7; p++) s0 = fmaf(tr[p], u[p], s0);
#pragma unroll
            for (int p = 7; p < T; p++) s1 = fmaf(tr[p], u[p], s1);
            float inv = __fdividef(1.0f, cm);
            float un = (s0 + s1) * inv * aux[l * 16 + n];
            if (n == 0) o += __logf(cm);
            Ubuf[b ^ 1][c * 16 + n] = un;
            __syncthreads();
            b ^= 1;
        }
    } else {
        for (int l = 0; l < CB; l++) {
            float u[T];
            ld14(&Ubuf[b][c * 16], u);
            float a[T];
#pragma unroll
            for (int p = 0; p < T; p++) a[p] = u[p] + tr[p];
            Ubuf[b ^ 1][c * 16 + n] = max14(a) + aux[l * 16 + n];
            __syncthreads();
            b ^= 1;
        }
    }
    if (n == 0) o_s[c] = o;
    __syncthreads();
    if (fwd) {
        float oc = o_s[c];
        float Uv = Ubuf[b][c * 16 + n];
        float Cf = (Uv > 0.0f) ? __logf(Uv) + oc + fsum_s : NINF;
        Msm[n * 16 + c] = Cf;
        __syncthreads();
        float r[T];
        ld14(&Msm[n * 16], r);
        float rm = max14(r);
        g_Em[chunk * 224 + n * 16 + c] = __expf(Cf - rm);
        if (c == 0) g_m[chunk * 16 + n] = rm;
    } else {
        g_Cv[chunk * 224 + n * 16 + c] = Ubuf[b][c * 16 + n];
    }
}

// ---------------- K3: combine 16 chunk mats -> supernode mats ----------------
__global__ void k_super(void) {
    __shared__ __align__(16) float Vb[2][224];     // transposed [c*16+n]
    __shared__ __align__(16) float Asm[224];
    __shared__ __align__(16) float Tt[224];
    __shared__ __align__(16) float Msm[224];
    __shared__ float o_s[16];
    int fwd = (blockIdx.x < SUPER);
    int s = fwd ? blockIdx.x : blockIdx.x - SUPER;
    int tid = threadIdx.x;                          // 196
    int n = tid % T, c = tid / T;
    Vb[0][c * 16 + n] = fwd ? ((n == c) ? 1.0f : 0.0f)
                            : ((n == c) ? 0.0f : NINF);
    float o = 0.0f;
    int b = 0;
    for (int k = 0; k < SCH; k++) {
        int ch = s * SCH + k;
        {   const float4* src = (const float4*)(fwd ? (g_Em + ch * 224)
                                                    : (g_Cv + ch * 224));
            float4* dst = (float4*)Asm;
            for (int i = tid; i < 56; i += 196) dst[i] = src[i];
        }
        float mk = fwd ? g_m[ch * 16 + n] : 0.0f;
        __syncthreads();
        float u[T], row[T];
        ld14(&Vb[b][c * 16], u);
        ld14(&Asm[n * 16], row);
        if (fwd) {
            float s0 = 0.0f, s1 = 0.0f;
#pragma unroll
            for (int p = 0; p < 7; p++) s0 = fmaf(row[p], u[p], s0);
#pragma unroll
            for (int p = 7; p < T; p++) s1 = fmaf(row[p], u[p], s1);
            float t = mk + __logf(fmaxf(s0 + s1, 1e-38f));
            Tt[c * 16 + n] = t;
            __syncthreads();
            float tc[T];
            ld14(&Tt[c * 16], tc);
            float cmax = max14(tc);
            Vb[b ^ 1][c * 16 + n] = __expf(t - cmax);
            if (n == 0) o += cmax;
            __syncthreads();
        } else {
            float a[T];
#pragma unroll
            for (int p = 0; p < T; p++) a[p] = row[p] + u[p];
            Vb[b ^ 1][c * 16 + n] = max14(a);
            __syncthreads();
        }
        b ^= 1;
    }
    if (n == 0) o_s[c] = o;
    __syncthreads();
    if (fwd) {
        float oc = o_s[c];
        float Vv = Vb[b][c * 16 + n];
        float Sl = (Vv > 0.0f) ? __logf(Vv) + oc : NINF;
        Msm[n * 16 + c] = Sl;
        __syncthreads();
        float r[T];
        ld14(&Msm[n * 16], r);
        float rm = max14(r);
        g_SEm[s * 224 + n * 16 + c] = __expf(Sl - rm);
        if (c == 0) g_Sm[s * 16 + n] = rm;
    } else {
        g_SCv[s * 224 + n * 16 + c] = Vb[b][c * 16 + n];
    }
}

// ---------------- K4: 16-step scans (fwd score | viterbi supernode starts) ---
__global__ void k_scan(const float* __restrict__ trans, float* __restrict__ out) {
    int lane = threadIdx.x;
    if (lane >= 16) return;
    const unsigned M16 = 0xFFFFu;
    if (blockIdx.x == 0) {
        // forward: linear vector scan over supernode mats
        float u = (lane == START_TAG) ? 1.0f : 0.0f;   // exp(init) (e^-10000 -> 0)
        float O = 0.0f;
        for (int i = 0; i < SUPER; i++) {
            float row[T]; float mk;
            if (lane < T) { ld14(g_SEm + i * 224 + lane * 16, row); mk = g_Sm[i * 16 + lane]; }
            else {
#pragma unroll
                for (int p = 0; p < T; p++) row[p] = 0.0f;
                mk = -3e38f;
            }
            float w = 0.0f;
#pragma unroll
            for (int p = 0; p < T; p++) {
                float up = __shfl_sync(M16, u, p, 16);
                w = fmaf(row[p], up, w);
            }
            float t = mk + __logf(fmaxf(w, 1e-38f));
            float M = t;
#pragma unroll
            for (int d = 8; d; d >>= 1) M = fmaxf(M, __shfl_xor_sync(M16, M, d, 16));
            u = __expf(t - M);
            O += M;
        }
        float v = (lane < T) ? (((u > 0.0f) ? __logf(u) : NINF) + O +
                                trans[STOP_TAG * T + lane])
                             : -3e38f;
        float M2 = v;
#pragma unroll
        for (int d = 8; d; d >>= 1) M2 = fmaxf(M2, __shfl_xor_sync(M16, M2, d, 16));
        float e = __expf(v - M2);
#pragma unroll
        for (int d = 8; d; d >>= 1) e += __shfl_xor_sync(M16, e, d, 16);
        float fwd_score = M2 + __logf(e);
        float gp = 0.0f;
        for (int j = lane; j < 256; j += 16) gp += g_goldpart[j];
#pragma unroll
        for (int d = 8; d; d >>= 1) gp += __shfl_xor_sync(M16, gp, d, 16);
        if (lane == 0) out[0] = fwd_score - gp;        // nll
    } else {
        // viterbi: max-plus vector scan, record vector at each supernode start
        float v = (lane == START_TAG) ? 0.0f : NEGV;
        for (int i = 0; i < SUPER; i++) {
            g_vsuper[i * 16 + lane] = (lane < T) ? v : NEGV;
            float row[T];
            if (lane < T) ld14(g_SCv + i * 224 + lane * 16, row);
            else {
#pragma unroll
                for (int p = 0; p < T; p++) row[p] = NINF;
            }
            float nv = -3e38f;
#pragma unroll
            for (int p = 0; p < T; p++) {
                float vp = __shfl_sync(M16, v, p, 16);
                nv = fmaxf(nv, row[p] + vp);
            }
            v = (lane < T) ? nv : NEGV;
        }
    }
}

// ---------------- K5: per-chunk viterbi walk (vstart fixup + backpointers) ---
__global__ void k_bp(const float* __restrict__ trans, float* __restrict__ out) {
    __shared__ __align__(16) float feat_s[CB * 16];
    __shared__ __align__(16) unsigned char bp_s[CB * T];
    __shared__ float term_s[T];
    int chunk = blockIdx.x;
    int tid = threadIdx.x;                          // 64
    {   const float4* src = (const float4*)(g_featsP + chunk * CB * 16);
        float4* dst = (float4*)feat_s;
        for (int i = tid; i < CB * 4; i += 64) dst[i] = src[i];
    }
    __syncthreads();
    if (tid < T) {
        int lane = tid;
        int sup = chunk >> 4;
        float v = g_vsuper[sup * 16 + lane];
        for (int k = (sup << 4); k < chunk; k++) {   // <=15 max-plus mat-vecs
            float row[T];
            ld14(g_Cv + k * 224 + lane * 16, row);
            float nv = NINF;
#pragma unroll
            for (int p = 0; p < T; p++) {
                float vp = __shfl_sync(0x3FFFu, v, p);
                nv = fmaxf(nv, row[p] + vp);
            }
            v = nv;
        }
        float tr[T];
#pragma unroll
        for (int p = 0; p < T; p++) tr[p] = trans[lane * T + p];
        float fv = v;
        for (int l = 0; l < CB; l++) {
            float best = NINF; int arg = 0;
#pragma unroll
            for (int p = 0; p < T; p++) {
                float vp = __shfl_sync(0x3FFFu, fv, p);
                float a2 = vp + tr[p];
                if (a2 > best) { best = a2; arg = p; }   // first-max == jnp.argmax
            }
            bp_s[l * T + lane] = (unsigned char)arg;
            fv = best + feat_s[l * 16 + lane];
        }
        __syncwarp(0x3FFFu);
        int t = lane;                                  // chunk backtrace map
        for (int l = CB - 1; l >= 0; l--) t = bp_s[l * T + t];
        g_F[chunk * T + lane] = (unsigned char)t;
        if (chunk == CHUNKS - 1) {
            term_s[lane] = fv + trans[STOP_TAG * T + lane];
            __syncwarp(0x3FFFu);
            if (lane == 0) {
                float best = -3e38f; int arg = 0;
#pragma unroll
                for (int nn = 0; nn < T; nn++) {
                    float tv = term_s[nn];
                    if (tv > best) { best = tv; arg = nn; }
                }
                g_best_last[0] = arg;
                out[1] = best;                          // path_score
            }
        }
    }
    __syncthreads();
    {   // vectorized writeback of backpointers (1792 B)
        int4* dst = (int4*)(g_bp + chunk * CB * T);
        const int4* src = (const int4*)bp_s;
        for (int i = tid; i < 112; i += 64) dst[i] = src[i];
    }
}

// ---------------- K6: carry chain over chunk maps ----------------------------
__global__ void k_carry(void) {
    __shared__ unsigned char F_s[CHUNKS * T];
    int tid = threadIdx.x;                          // 256
    for (int i = tid; i < CHUNKS * T; i += 256) F_s[i] = g_F[i];
    __syncthreads();
    if (tid == 0) {
        int cc = g_best_last[0];
        for (int i = CHUNKS - 1; i >= 0; i--) {
            g_carry[i] = cc;
            cc = F_s[i * T + cc];
        }
    }
}

// ---------------- K7: emit path ----------------------------------------------
__global__ void k_path(float* __restrict__ out) {
    __shared__ unsigned char bp_s[CB * T];
    int chunk = blockIdx.x;
    int tid = threadIdx.x;                          // 64
    for (int i = tid; i < CB * T; i += 64)
        bp_s[i] = g_bp[chunk * CB * T + i];
    __syncthreads();
    if (tid == 0) {
        int cc = g_carry[chunk];
        for (int l = CB - 1; l >= 0; l--) {
            out[2 + chunk * CB + l] = (float)cc;
            cc = bp_s[l * T + cc];
        }
    }
}

// ---------------- launch -----------------------------------------------------
extern "C" void kernel_launch(void* const* d_in, const int* in_sizes, int n_in,
                              void* d_out, int out_size) {
    const int*   sent  = (const int*)d_in[0];
    const int*   tags  = (const int*)d_in[1];
    const float* emb   = (const float*)d_in[2];
    const float* W     = (const float*)d_in[3];
    const float* trans = (const float*)d_in[4];
    float* out = (float*)d_out;
    (void)in_sizes; (void)n_in; (void)out_size;

    k_feats<<<LSEQ / 128, 128>>>(sent, tags, emb, W, trans);
    k_chunks<<<2 * CHUNKS, 196>>>(trans);
    k_super<<<2 * SUPER, 196>>>();
    k_scan<<<2, 32>>>(trans, out);
    k_bp<<<CHUNKS, 64>>>(trans, out);
    k_carry<<<1, 256>>>();
    k_path<<<CHUNKS, 64>>>(out);
}

// round 5
// speedup vs baseline: 2.4925x; 1.2117x over previous
#include <cuda_runtime.h>

#define LSEQ 32768
#define T 14
#define EMB 300
#define CHUNKS 512
#define CB 64             // chunk length (CHUNKS*CB == LSEQ)
#define SUPER 32          // supernodes per side
#define SCH 16            // chunks per supernode
#define START_TAG 12
#define STOP_TAG 13
#define NEGV (-10000.0f)
#define NINF (-1e30f)

// ---------------- scratch (static device globals; no allocation) -------------
__device__ float g_featsP[LSEQ * 16];          // feats padded to 16
__device__ float g_goldpart[256];
__device__ float g_Em[CHUNKS * 224];           // fwd chunk mats (linear, row-norm)
__device__ float g_m[CHUNKS * 16];             // row log-offsets for g_Em
__device__ float g_Cv[CHUNKS * 224];           // viterbi chunk mats (max-plus)
__device__ float g_SEm[SUPER * 224];           // supernode fwd mats
__device__ float g_Sm[SUPER * 16];
__device__ float g_SCv[SUPER * 224];           // supernode viterbi mats
__device__ float g_vsuper[SUPER * 16];         // viterbi vec at supernode starts
__device__ int   g_best_last;
__device__ unsigned char g_F[CHUNKS * T];      // per-chunk backtrace maps
__device__ int   g_carry[CHUNKS];
// dataflow counters (reset by the PRECEDING kernel each replay)
__device__ int   g_cntc[2 * SUPER];            // per-side per-super chunk counters
__device__ int   g_cnts[2];                    // per-side super counters
__device__ int   g_cnt_bp;
__device__ int   g_flag;

__device__ __forceinline__ void ld14(const float* p, float* u) {
    const float4* q = (const float4*)p;
    float4 a = q[0], b = q[1], c = q[2], d = q[3];
    u[0]=a.x; u[1]=a.y; u[2]=a.z; u[3]=a.w;
    u[4]=b.x; u[5]=b.y; u[6]=b.z; u[7]=b.w;
    u[8]=c.x; u[9]=c.y; u[10]=c.z; u[11]=c.w;
    u[12]=d.x; u[13]=d.y;
}
__device__ __forceinline__ void ld14cg(const float* p, float* u) {
    const float4* q = (const float4*)p;
    float4 a = __ldcg(q), b = __ldcg(q+1), c = __ldcg(q+2), d = __ldcg(q+3);
    u[0]=a.x; u[1]=a.y; u[2]=a.z; u[3]=a.w;
    u[4]=b.x; u[5]=b.y; u[6]=b.z; u[7]=b.w;
    u[8]=c.x; u[9]=c.y; u[10]=c.z; u[11]=c.w;
    u[12]=d.x; u[13]=d.y;
}
__device__ __forceinline__ float max14(const float* u) {
    float a0=fmaxf(u[0],u[1]), a1=fmaxf(u[2],u[3]), a2=fmaxf(u[4],u[5]);
    float a3=fmaxf(u[6],u[7]), a4=fmaxf(u[8],u[9]), a5=fmaxf(u[10],u[11]);
    float a6=fmaxf(u[12],u[13]);
    float b0=fmaxf(a0,a1), b1=fmaxf(a2,a3), b2=fmaxf(a4,a5);
    return fmaxf(fmaxf(b0,b1), fmaxf(b2,a6));
}
// first-max argmax (ties -> lowest index), depth-4 tree
__device__ __forceinline__ void amax14(const float* a, float& best, int& arg) {
    float v[7]; int ix[7];
#pragma unroll
    for (int p = 0; p < 7; p++) {
        bool t = a[2*p] >= a[2*p+1];
        v[p] = t ? a[2*p] : a[2*p+1];
        ix[p] = t ? 2*p : 2*p+1;
    }
    bool t0 = v[0] >= v[1]; float w0 = t0?v[0]:v[1]; int j0 = t0?ix[0]:ix[1];
    bool t1 = v[2] >= v[3]; float w1 = t1?v[2]:v[3]; int j1 = t1?ix[2]:ix[3];
    bool t2 = v[4] >= v[5]; float w2 = t2?v[4]:v[5]; int j2 = t2?ix[4]:ix[5];
    bool s0 = w0 >= w1; float x0 = s0?w0:w1; int y0 = s0?j0:j1;
    bool s1 = w2 >= v[6]; float x1 = s1?w2:v[6]; int y1 = s1?j2:ix[6];
    bool s2 = x0 >= x1; best = s2?x0:x1; arg = s2?y0:y1;
}

// ---------------- K1: feats + fused gold + counter resets --------------------
__global__ void k_feats(const int* __restrict__ sent, const int* __restrict__ tags,
                        const float* __restrict__ emb, const float* __restrict__ W,
                        const float* __restrict__ trans) {
    __shared__ __align__(16) float Ws[T * EMB];
    __shared__ float red[128];
    if (blockIdx.x == 0) {
        if (threadIdx.x < 2 * SUPER) g_cntc[threadIdx.x] = 0;
        if (threadIdx.x < 2) g_cnts[threadIdx.x] = 0;
    }
    for (int i = threadIdx.x; i < T * EMB; i += 128) Ws[i] = W[i];
    __syncthreads();
    int l = blockIdx.x * 128 + threadIdx.x;
    const float4* e4 = (const float4*)(emb + (size_t)sent[l] * EMB);
    float acc[T];
#pragma unroll
    for (int t = 0; t < T; t++) acc[t] = 0.0f;
    for (int k = 0; k < EMB / 4; k++) {
        float4 ev = e4[k];
#pragma unroll
        for (int t = 0; t < T; t++) {
            float4 wv = *(const float4*)(Ws + t * EMB + 4 * k);
            float a = acc[t];
            a = fmaf(ev.x, wv.x, a); a = fmaf(ev.y, wv.y, a);
            a = fmaf(ev.z, wv.z, a); a = fmaf(ev.w, wv.w, a);
            acc[t] = a;
        }
    }
#pragma unroll
    for (int t = 0; t < T; t++) g_featsP[l * 16 + t] = acc[t];
    int tg = tags[l];
    int prev = (l == 0) ? START_TAG : tags[l - 1];
    float emit = 0.0f;
#pragma unroll
    for (int t = 0; t < T; t++) if (t == tg) emit = acc[t];
    float gv = trans[tg * T + prev] + emit;
    if (l == LSEQ - 1) gv += trans[STOP_TAG * T + tg];
    red[threadIdx.x] = gv;
    __syncthreads();
    for (int off = 64; off; off >>= 1) {
        if (threadIdx.x < off) red[threadIdx.x] += red[threadIdx.x + off];
        __syncthreads();
    }
    if (threadIdx.x == 0) g_goldpart[blockIdx.x] = red[0];
}

// ---------------- K2: fused chunks -> supernodes -> scans --------------------
// grid = 2*CHUNKS (chunk blocks) + 2*SUPER (super blocks) + 2 (scan blocks)
// side 0 = viterbi, side 1 = forward. Dependents have higher bids.
__global__ void __launch_bounds__(196) k_mid(const float* __restrict__ trans,
                                             float* __restrict__ out) {
    __shared__ __align__(16) float Ubuf[2][224];
    __shared__ __align__(16) float aux[CB * 16];
    __shared__ __align__(16) float Etr_s[224];
    __shared__ __align__(16) float Msm[224];
    __shared__ float fmaxs[CB];
    __shared__ float o_s[16];
    __shared__ float fsum_s;
    int bid = blockIdx.x, tid = threadIdx.x;
    if (bid == 0 && tid == 0) { g_cnt_bp = 0; g_flag = 0; }  // resets for k_tail

    if (bid < 2 * CHUNKS) {
        // ======== chunk role ========
        int side = (bid < CHUNKS) ? 0 : 1;
        int chunk = (side == 0) ? bid : bid - CHUNKS;
        int fwd = side;
        int n = tid % T, c = tid / T;
        {   int nn = tid / T, pp = tid % T;
            float tv = trans[nn * T + pp];
            Etr_s[nn * 16 + pp] = fwd ? __expf(tv) : tv; }
        if (fwd) {
            if (tid < CB) {
                float f[T];
                ld14(g_featsP + (chunk * CB + tid) * 16, f);
                float fm = max14(f);
                fmaxs[tid] = fm;
#pragma unroll
                for (int j = 0; j < T; j++) aux[tid * 16 + j] = __expf(f[j] - fm);
            }
        } else {
            const float4* src = (const float4*)(g_featsP + chunk * CB * 16);
            float4* dst = (float4*)aux;
            for (int i = tid; i < CB * 4; i += 196) dst[i] = src[i];
        }
        Ubuf[0][c * 16 + n] = fwd ? ((n == c) ? 1.0f : 0.0f)
                                  : ((n == c) ? 0.0f : NINF);
        __syncthreads();
        float tr[T];
#pragma unroll
        for (int p = 0; p < T; p++) tr[p] = Etr_s[n * 16 + p];
        float o = 0.0f; int b = 0;
        if (fwd) {
            for (int l = 0; l < CB; l++) {
                float u[T]; ld14(&Ubuf[b][c * 16], u);
                float cm = fmaxf(max14(u), 1e-35f);
                float s0 = 0.0f, s1 = 0.0f;
#pragma unroll
                for (int p = 0; p < 7; p++) s0 = fmaf(tr[p], u[p], s0);
#pragma unroll
                for (int p = 7; p < T; p++) s1 = fmaf(tr[p], u[p], s1);
                float un = (s0 + s1) * __fdividef(1.0f, cm) * aux[l * 16 + n];
                if (n == 0) o += __logf(cm);
                Ubuf[b ^ 1][c * 16 + n] = un;
                __syncthreads(); b ^= 1;
            }
        } else {
            for (int l = 0; l < CB; l++) {
                float u[T]; ld14(&Ubuf[b][c * 16], u);
                float a[T];
#pragma unroll
                for (int p = 0; p < T; p++) a[p] = u[p] + tr[p];
                Ubuf[b ^ 1][c * 16 + n] = max14(a) + aux[l * 16 + n];
                __syncthreads(); b ^= 1;
            }
        }
        if (n == 0) o_s[c] = o;
        if (fwd && tid == 0) {
            float s = 0.0f;
            for (int l2 = 0; l2 < CB; l2++) s += fmaxs[l2];
            fsum_s = s;
        }
        __syncthreads();
        if (fwd) {
            float Uv = Ubuf[b][c * 16 + n];
            float Cf = (Uv > 0.0f) ? __logf(Uv) + o_s[c] + fsum_s : NINF;
            Msm[n * 16 + c] = Cf;
            __syncthreads();
            float r[T]; ld14(&Msm[n * 16], r);
            float rm = max14(r);
            g_Em[chunk * 224 + n * 16 + c] = __expf(Cf - rm);
            if (c == 0) g_m[chunk * 16 + n] = rm;
        } else {
            g_Cv[chunk * 224 + n * 16 + c] = Ubuf[b][c * 16 + n];
        }
        __threadfence(); __syncthreads();
        if (tid == 0) atomicAdd(&g_cntc[side * SUPER + (chunk >> 4)], 1);

    } else if (bid < 2 * CHUNKS + 2 * SUPER) {
        // ======== supernode role ========
        int idx = bid - 2 * CHUNKS;
        int side = (idx < SUPER) ? 0 : 1;
        int s = (side == 0) ? idx : idx - SUPER;
        if (tid == 0) {
            while (atomicAdd(&g_cntc[side * SUPER + s], 0) < SCH) __nanosleep(64);
        }
        __syncthreads(); __threadfence();
        int n = tid % T, c = tid / T;
        Ubuf[0][c * 16 + n] = side ? ((n == c) ? 1.0f : 0.0f)
                                   : ((n == c) ? 0.0f : NINF);
        float o = 0.0f; int b = 0;
        __syncthreads();
        for (int k = 0; k < SCH; k++) {
            int ch = s * SCH + k;
            {   const float4* src = (const float4*)(side ? (g_Em + ch * 224)
                                                         : (g_Cv + ch * 224));
                float4* dst = (float4*)Etr_s;
                for (int i = tid; i < 56; i += 196) dst[i] = __ldcg(src + i); }
            float mk = side ? __ldcg(g_m + ch * 16 + n) : 0.0f;
            __syncthreads();
            float u[T], row[T];
            ld14(&Ubuf[b][c * 16], u);
            ld14(&Etr_s[n * 16], row);
            if (side) {
                float s0 = 0.0f, s1 = 0.0f;
#pragma unroll
                for (int p = 0; p < 7; p++) s0 = fmaf(row[p], u[p], s0);
#pragma unroll
                for (int p = 7; p < T; p++) s1 = fmaf(row[p], u[p], s1);
                float t = mk + __logf(fmaxf(s0 + s1, 1e-38f));
                Msm[c * 16 + n] = t;
                __syncthreads();
                float tc[T]; ld14(&Msm[c * 16], tc);
                float cmax = max14(tc);
                Ubuf[b ^ 1][c * 16 + n] = __expf(t - cmax);
                if (n == 0) o += cmax;
                __syncthreads();
            } else {
                float a[T];
#pragma unroll
                for (int p = 0; p < T; p++) a[p] = row[p] + u[p];
                Ubuf[b ^ 1][c * 16 + n] = max14(a);
                __syncthreads();
            }
            b ^= 1;
        }
        if (n == 0) o_s[c] = o;
        __syncthreads();
        if (side) {
            float Vv = Ubuf[b][c * 16 + n];
            float Sl = (Vv > 0.0f) ? __logf(Vv) + o_s[c] : NINF;
            Msm[n * 16 + c] = Sl;
            __syncthreads();
            float r[T]; ld14(&Msm[n * 16], r);
            float rm = max14(r);
            g_SEm[s * 224 + n * 16 + c] = __expf(Sl - rm);
            if (c == 0) g_Sm[s * 16 + n] = rm;
        } else {
            g_SCv[s * 224 + n * 16 + c] = Ubuf[b][c * 16 + n];
        }
        __threadfence(); __syncthreads();
        if (tid == 0) atomicAdd(&g_cnts[side], 1);

    } else {
        // ======== scan role (1 vit block, 1 fwd block) ========
        int side = (bid == 2 * CHUNKS + 2 * SUPER) ? 0 : 1;
        if (tid == 0) {
            while (atomicAdd(&g_cnts[side], 0) < SUPER) __nanosleep(64);
        }
        __syncthreads(); __threadfence();
        int lane = tid;
        if (lane < 16) {
            const unsigned M16 = 0xFFFFu;
            if (side == 0) {
                float v = (lane == START_TAG) ? 0.0f : NEGV;
                float row[T], nrow[T];
                if (lane < T) ld14cg(g_SCv + lane * 16, row);
                else { for (int p = 0; p < T; p++) row[p] = NINF; }
                for (int i = 0; i < SUPER; i++) {
                    g_vsuper[i * 16 + lane] = (lane < T) ? v : NEGV;
                    if (i + 1 < SUPER) {
                        if (lane < T) ld14cg(g_SCv + (i + 1) * 224 + lane * 16, nrow);
                        else { for (int p = 0; p < T; p++) nrow[p] = NINF; }
                    }
                    float nv = -3e38f;
#pragma unroll
                    for (int p = 0; p < T; p++) {
                        float vp = __shfl_sync(M16, v, p, 16);
                        nv = fmaxf(nv, row[p] + vp);
                    }
                    v = (lane < T) ? nv : NEGV;
#pragma unroll
                    for (int p = 0; p < T; p++) row[p] = nrow[p];
                }
            } else {
                float u = (lane == START_TAG) ? 1.0f : 0.0f;
                float O = 0.0f;
                float row[T], nrow[T], mk, nmk;
                if (lane < T) { ld14cg(g_SEm + lane * 16, row); mk = __ldcg(g_Sm + lane); }
                else { for (int p = 0; p < T; p++) row[p] = 0.0f; mk = -3e38f; }
                for (int i = 0; i < SUPER; i++) {
                    if (i + 1 < SUPER) {
                        if (lane < T) { ld14cg(g_SEm + (i + 1) * 224 + lane * 16, nrow);
                                        nmk = __ldcg(g_Sm + (i + 1) * 16 + lane); }
                        else { for (int p = 0; p < T; p++) nrow[p] = 0.0f; nmk = -3e38f; }
                    }
                    float w = 0.0f;
#pragma unroll
                    for (int p = 0; p < T; p++) {
                        float up = __shfl_sync(M16, u, p, 16);
                        w = fmaf(row[p], up, w);
                    }
                    float t = mk + __logf(fmaxf(w, 1e-38f));
                    float M = t;
#pragma unroll
                    for (int d = 8; d; d >>= 1) M = fmaxf(M, __shfl_xor_sync(M16, M, d, 16));
                    u = __expf(t - M);
                    O += M;
#pragma unroll
                    for (int p = 0; p < T; p++) row[p] = nrow[p];
                    mk = nmk;
                }
                float val = (lane < T) ? (((u > 0.0f) ? __logf(u) : NINF) + O +
                                          trans[STOP_TAG * T + lane])
                                       : -3e38f;
                float M2 = val;
#pragma unroll
                for (int d = 8; d; d >>= 1) M2 = fmaxf(M2, __shfl_xor_sync(M16, M2, d, 16));
                float e = __expf(val - M2);
#pragma unroll
                for (int d = 8; d; d >>= 1) e += __shfl_xor_sync(M16, e, d, 16);
                float fwd_score = M2 + __logf(e);
                float gp = 0.0f;
                for (int j = lane; j < 256; j += 16) gp += g_goldpart[j];
#pragma unroll
                for (int d = 8; d; d >>= 1) gp += __shfl_xor_sync(M16, gp, d, 16);
                if (lane == 0) out[0] = fwd_score - gp;   // nll
            }
        }
    }
}

// ---------------- K3: fused bp -> carry -> path ------------------------------
__global__ void __launch_bounds__(128) k_tail(const float* __restrict__ trans,
                                              float* __restrict__ out) {
    __shared__ __align__(16) float feat_s[CB * 16];
    __shared__ __align__(16) unsigned char bp_s[CB * T];
    __shared__ __align__(16) unsigned char Fs[CHUNKS * T];   // 7168 B
    __shared__ unsigned char comp_s[8 * T];
    __shared__ float term_s[T];
    __shared__ int sgrp[9];
    __shared__ int role;
    int chunk = blockIdx.x, tid = threadIdx.x;
    {   const float4* src = (const float4*)(g_featsP + chunk * CB * 16);
        float4* dst = (float4*)feat_s;
        for (int i = tid; i < CB * 4; i += 128) dst[i] = src[i]; }
    __syncthreads();
    if (tid < T) {
        int lane = tid;
        int sup = chunk >> 4;
        float v = g_vsuper[sup * 16 + lane];
        for (int k = sup * SCH; k < chunk; k++) {     // <=15 max-plus mat-vecs
            float row[T]; ld14(g_Cv + k * 224 + lane * 16, row);
            float fvall[T];
#pragma unroll
            for (int p = 0; p < T; p++) fvall[p] = __shfl_sync(0x3FFFu, v, p);
            float nv = NINF;
#pragma unroll
            for (int p = 0; p < T; p++) nv = fmaxf(nv, row[p] + fvall[p]);
            v = nv;
        }
        float tr[T];
#pragma unroll
        for (int p = 0; p < T; p++) tr[p] = trans[lane * T + p];
        float fv = v;
        for (int l = 0; l < CB; l++) {
            float fvall[T];
#pragma unroll
            for (int p = 0; p < T; p++) fvall[p] = __shfl_sync(0x3FFFu, fv, p);
            float a[T];
#pragma unroll
            for (int p = 0; p < T; p++) a[p] = fvall[p] + tr[p];
            float best; int arg;
            amax14(a, best, arg);
            bp_s[l * T + lane] = (unsigned char)arg;
            fv = best + feat_s[l * 16 + lane];
        }
        __syncwarp(0x3FFFu);
        int t = lane;
        for (int l = CB - 1; l >= 0; l--) t = bp_s[l * T + t];
        g_F[chunk * T + lane] = (unsigned char)t;
        if (chunk == CHUNKS - 1) {
            term_s[lane] = fv + trans[STOP_TAG * T + lane];
            __syncwarp(0x3FFFu);
            if (lane == 0) {
                float a2[T];
#pragma unroll
                for (int p = 0; p < T; p++) a2[p] = term_s[p];
                float best; int arg;
                amax14(a2, best, arg);
                g_best_last = arg;
                out[1] = best;                      // path_score
            }
        }
    }
    __threadfence(); __syncthreads();
    if (tid == 0) {
        int old = atomicAdd(&g_cnt_bp, 1);
        role = (old == CHUNKS - 1);
    }
    __syncthreads();
    if (role) {
        __threadfence();
        {   const int4* src = (const int4*)g_F;
            int4* dst = (int4*)Fs;
            for (int i = tid; i < (CHUNKS * T) / 16; i += 128) dst[i] = __ldcg(src + i); }
        __syncthreads();
        // Phase A: per-group (64 chunks) suffix composition applied to each tag
        if (tid < 8 * T) {
            int g = tid / T, x = tid % T;
            int t = x;
            for (int l = g * 64 + 63; l >= g * 64; l--) t = Fs[l * T + t];
            comp_s[g * T + x] = (unsigned char)t;
        }
        __syncthreads();
        // Phase B: 8-step chain over groups
        if (tid == 0) {
            int sgv = g_best_last;
            sgrp[8] = sgv;
            for (int g = 7; g >= 0; g--) { sgv = comp_s[g * T + sgv]; sgrp[g] = sgv; }
        }
        __syncthreads();
        // Phase C: fill carries within each group (8 parallel chains)
        if (tid < 8) {
            int g = tid;
            int t = sgrp[g + 1];
            for (int l = g * 64 + 63; l >= g * 64; l--) {
                g_carry[l] = t;
                t = Fs[l * T + t];
            }
        }
        __threadfence(); __syncthreads();
        if (tid == 0) atomicExch(&g_flag, 1);
    } else {
        if (tid == 0) { while (atomicAdd(&g_flag, 0) == 0) __nanosleep(128); }
        __syncthreads();
    }
    __threadfence();
    if (tid == 0) {
        int cc = g_carry[chunk];
        for (int l = CB - 1; l >= 0; l--) {
            out[2 + chunk * CB + l] = (float)cc;
            cc = bp_s[l * T + cc];
        }
    }
}

// ---------------- launch -----------------------------------------------------
extern "C" void kernel_launch(void* const* d_in, const int* in_sizes, int n_in,
                              void* d_out, int out_size) {
    const int*   sent  = (const int*)d_in[0];
    const int*   tags  = (const int*)d_in[1];
    const float* emb   = (const float*)d_in[2];
    const float* W     = (const float*)d_in[3];
    const float* trans = (const float*)d_in[4];
    float* out = (float*)d_out;
    (void)in_sizes; (void)n_in; (void)out_size;

    k_feats<<<LSEQ / 128, 128>>>(sent, tags, emb, W, trans);
    k_mid<<<2 * CHUNKS + 2 * SUPER + 2, 196>>>(trans, out);
    k_tail<<<CHUNKS, 128>>>(trans, out);
}

// round 6
// speedup vs baseline: 2.5078x; 1.0061x over previous
#include <cuda_runtime.h>

#define LSEQ 32768
#define T 14
#define EMB 300
#define CHUNKS 512
#define CB 64             // chunk length (CHUNKS*CB == LSEQ)
#define SUPER 32          // supernodes per side
#define SCH 16            // chunks per supernode
#define START_TAG 12
#define STOP_TAG 13
#define NEGV (-10000.0f)
#define NINF (-1e30f)

#define NB_F CHUNKS       // feats blocks: one per chunk (64 positions each)
#define BID_VCH NB_F                  // vit chunk blocks  [512,1024)
#define BID_FCH (BID_VCH + CHUNKS)    // fwd chunk blocks  [1024,1536)
#define BID_SUP (BID_FCH + CHUNKS)    // super blocks      [1536,1600)
#define BID_SCAN (BID_SUP + 2*SUPER)  // scan blocks       1600,1601
#define GRID_MID (BID_SCAN + 2)

// ---------------- scratch (static device globals; no allocation) -------------
__device__ float g_featsP[LSEQ * 16];
__device__ float g_goldpart[NB_F];
__device__ float g_Em[CHUNKS * 224];           // fwd chunk mats (linear, row-norm)
__device__ float g_m[CHUNKS * 16];
__device__ float g_Cv[CHUNKS * 224];           // viterbi chunk mats
__device__ float g_SEm[SUPER * 224];
__device__ float g_Sm[SUPER * 16];
__device__ float g_SCv[SUPER * 224];
__device__ float g_vsuper[SUPER * 16];
__device__ int   g_best_last;
__device__ unsigned char g_F[CHUNKS * T];
__device__ int   g_carry[CHUNKS];
// dataflow counters: g_cntF/g_cntc/g_cnts reset by k_tail (after all uses);
// g_cnt_bp/g_flag reset by k_mid block 0 (before k_tail uses them).
__device__ int   g_cntF[CHUNKS];
__device__ int   g_cntc[2 * SUPER];
__device__ int   g_cnts[2];
__device__ int   g_cnt_bp;
__device__ int   g_flag;

__device__ __forceinline__ void ld14(const float* p, float* u) {
    const float4* q = (const float4*)p;
    float4 a = q[0], b = q[1], c = q[2], d = q[3];
    u[0]=a.x; u[1]=a.y; u[2]=a.z; u[3]=a.w;
    u[4]=b.x; u[5]=b.y; u[6]=b.z; u[7]=b.w;
    u[8]=c.x; u[9]=c.y; u[10]=c.z; u[11]=c.w;
    u[12]=d.x; u[13]=d.y;
}
__device__ __forceinline__ void ld14cg(const float* p, float* u) {
    const float4* q = (const float4*)p;
    float4 a = __ldcg(q), b = __ldcg(q+1), c = __ldcg(q+2), d = __ldcg(q+3);
    u[0]=a.x; u[1]=a.y; u[2]=a.z; u[3]=a.w;
    u[4]=b.x; u[5]=b.y; u[6]=b.z; u[7]=b.w;
    u[8]=c.x; u[9]=c.y; u[10]=c.z; u[11]=c.w;
    u[12]=d.x; u[13]=d.y;
}
__device__ __forceinline__ float max14(const float* u) {
    float a0=fmaxf(u[0],u[1]), a1=fmaxf(u[2],u[3]), a2=fmaxf(u[4],u[5]);
    float a3=fmaxf(u[6],u[7]), a4=fmaxf(u[8],u[9]), a5=fmaxf(u[10],u[11]);
    float a6=fmaxf(u[12],u[13]);
    float b0=fmaxf(a0,a1), b1=fmaxf(a2,a3), b2=fmaxf(a4,a5);
    return fmaxf(fmaxf(b0,b1), fmaxf(b2,a6));
}
__device__ __forceinline__ void amax14(const float* a, float& best, int& arg) {
    float v[7]; int ix[7];
#pragma unroll
    for (int p = 0; p < 7; p++) {
        bool t = a[2*p] >= a[2*p+1];
        v[p] = t ? a[2*p] : a[2*p+1];
        ix[p] = t ? 2*p : 2*p+1;
    }
    bool t0 = v[0] >= v[1]; float w0 = t0?v[0]:v[1]; int j0 = t0?ix[0]:ix[1];
    bool t1 = v[2] >= v[3]; float w1 = t1?v[2]:v[3]; int j1 = t1?ix[2]:ix[3];
    bool t2 = v[4] >= v[5]; float w2 = t2?v[4]:v[5]; int j2 = t2?ix[4]:ix[5];
    bool s0 = w0 >= w1; float x0 = s0?w0:w1; int y0 = s0?j0:j1;
    bool s1 = w2 >= v[6]; float x1 = s1?w2:v[6]; int y1 = s1?j2:ix[6];
    bool s2 = x0 >= x1; best = s2?x0:x1; arg = s2?y0:y1;
}

struct ChunkS {
    float Ubuf[2][224];
    float aux[CB * 16];
    float Etr[224];
    float Msm[224];
    float fmaxs[CB];
    float o_s[16];
    float fsum;
};
struct FeatsS {
    float Ws[T * EMB];
    float red[256];
};
union SmemU { FeatsS f; ChunkS c; };

// ---------------- K1: fused feats -> chunks -> supernodes -> scans -----------
__global__ void __launch_bounds__(256) k_mid(const int* __restrict__ sent,
                                             const int* __restrict__ tags,
                                             const float* __restrict__ emb,
                                             const float* __restrict__ W,
                                             const float* __restrict__ trans,
                                             float* __restrict__ out) {
    __shared__ SmemU sm;
    int bid = blockIdx.x, tid = threadIdx.x;

    if (bid < NB_F) {
        // ======== feats role: 64 positions, 4 threads per position ========
        FeatsS& S = sm.f;
        if (bid == 0 && tid == 0) { g_cnt_bp = 0; g_flag = 0; }
        for (int i = tid; i < T * EMB; i += 256) S.Ws[i] = W[i];
        __syncthreads();
        int pos = bid * CB + (tid >> 2);
        int q = tid & 3;
        const float4* e4 = (const float4*)(emb + (size_t)__ldg(sent + pos) * EMB);
        float acc[T];
#pragma unroll
        for (int t = 0; t < T; t++) acc[t] = 0.0f;
#pragma unroll
        for (int j = 0; j < 19; j++) {
            int k = 4 * j + q;
            if (k < 75) {
                float4 ev = __ldg(e4 + k);
#pragma unroll
                for (int t = 0; t < T; t++) {
                    float4 wv = *(const float4*)(S.Ws + t * EMB + 4 * k);
                    float a = acc[t];
                    a = fmaf(ev.x, wv.x, a); a = fmaf(ev.y, wv.y, a);
                    a = fmaf(ev.z, wv.z, a); a = fmaf(ev.w, wv.w, a);
                    acc[t] = a;
                }
            }
        }
#pragma unroll
        for (int t = 0; t < T; t++) {
            acc[t] += __shfl_xor_sync(0xFFFFFFFFu, acc[t], 1, 4);
            acc[t] += __shfl_xor_sync(0xFFFFFFFFu, acc[t], 2, 4);
        }
        float4 st;
        st.x = (q==0)?acc[0]:(q==1)?acc[4]:(q==2)?acc[8]:acc[12];
        st.y = (q==0)?acc[1]:(q==1)?acc[5]:(q==2)?acc[9]:acc[13];
        st.z = (q==0)?acc[2]:(q==1)?acc[6]:(q==2)?acc[10]:0.0f;
        st.w = (q==0)?acc[3]:(q==1)?acc[7]:(q==2)?acc[11]:0.0f;
        ((float4*)(g_featsP + pos * 16))[q] = st;
        __threadfence();
        __syncthreads();
        if (tid == 0) atomicAdd(&g_cntF[bid], 1);   // release this chunk's feats
        // gold contribution (after the signal; cheap)
        float gv = 0.0f;
        if (q == 0) {
            int tg = __ldg(tags + pos);
            int prev = (pos == 0) ? START_TAG : __ldg(tags + pos - 1);
            float emit = 0.0f;
#pragma unroll
            for (int t = 0; t < T; t++) if (t == tg) emit = acc[t];
            gv = trans[tg * T + prev] + emit;
            if (pos == LSEQ - 1) gv += trans[STOP_TAG * T + tg];
        }
        S.red[tid] = gv;
        __syncthreads();
        for (int off = 128; off; off >>= 1) {
            if (tid < off) S.red[tid] += S.red[tid + off];
            __syncthreads();
        }
        if (tid == 0) g_goldpart[bid] = S.red[0];

    } else if (bid < BID_SUP) {
        // ======== chunk role ========
        ChunkS& S = sm.c;
        int side = (bid < BID_FCH) ? 0 : 1;           // 0 vit, 1 fwd
        int chunk = bid - (side ? BID_FCH : BID_VCH);
        int fwd = side;
        int active = (tid < 196);
        int n = tid % T, c = tid / T;
        if (active) {
            int nn = tid / T, pp = tid % T;
            float tv = trans[nn * T + pp];
            S.Etr[nn * 16 + pp] = fwd ? __expf(tv) : tv;
        }
        if (tid == 0) {
            while (atomicAdd(&g_cntF[chunk], 0) < 1) __nanosleep(32);
        }
        __syncthreads(); __threadfence();
        if (fwd) {
            if (tid < CB) {
                float f[T];
                ld14cg(g_featsP + (chunk * CB + tid) * 16, f);
                float fm = max14(f);
                S.fmaxs[tid] = fm;
#pragma unroll
                for (int j = 0; j < T; j++) S.aux[tid * 16 + j] = __expf(f[j] - fm);
            }
        } else {
            const float4* src = (const float4*)(g_featsP + chunk * CB * 16);
            float4* dst = (float4*)S.aux;
            for (int i = tid; i < CB * 4; i += 256) dst[i] = __ldcg(src + i);
        }
        if (active)
            S.Ubuf[0][c * 16 + n] = fwd ? ((n == c) ? 1.0f : 0.0f)
                                        : ((n == c) ? 0.0f : NINF);
        __syncthreads();
        float tr[T];
        if (active) {
#pragma unroll
            for (int p = 0; p < T; p++) tr[p] = S.Etr[n * 16 + p];
        }
        float o = 0.0f; int b = 0;
        if (fwd) {
            for (int l = 0; l < CB; l++) {
                if (active) {
                    float u[T]; ld14(&S.Ubuf[b][c * 16], u);
                    float cm = fmaxf(max14(u), 1e-35f);
                    float s0 = 0.0f, s1 = 0.0f;
#pragma unroll
                    for (int p = 0; p < 7; p++) s0 = fmaf(tr[p], u[p], s0);
#pragma unroll
                    for (int p = 7; p < T; p++) s1 = fmaf(tr[p], u[p], s1);
                    float un = (s0 + s1) * __fdividef(1.0f, cm) * S.aux[l * 16 + n];
                    if (n == 0) o += __logf(cm);
                    S.Ubuf[b ^ 1][c * 16 + n] = un;
                }
                __syncthreads(); b ^= 1;
            }
        } else {
            for (int l = 0; l < CB; l++) {
                if (active) {
                    float u[T]; ld14(&S.Ubuf[b][c * 16], u);
                    float a[T];
#pragma unroll
                    for (int p = 0; p < T; p++) a[p] = u[p] + tr[p];
                    S.Ubuf[b ^ 1][c * 16 + n] = max14(a) + S.aux[l * 16 + n];
                }
                __syncthreads(); b ^= 1;
            }
        }
        if (active && n == 0) S.o_s[c] = o;
        if (fwd && tid == 0) {
            float s = 0.0f;
            for (int l2 = 0; l2 < CB; l2++) s += S.fmaxs[l2];
            S.fsum = s;
        }
        __syncthreads();
        if (fwd) {
            if (active) {
                float Uv = S.Ubuf[b][c * 16 + n];
                float Cf = (Uv > 0.0f) ? __logf(Uv) + S.o_s[c] + S.fsum : NINF;
                S.Msm[n * 16 + c] = Cf;
            }
            __syncthreads();
            if (active) {
                float r[T]; ld14(&S.Msm[n * 16], r);
                float rm = max14(r);
                g_Em[chunk * 224 + n * 16 + c] = __expf(S.Msm[n * 16 + c] - rm);
                if (c == 0) g_m[chunk * 16 + n] = rm;
            }
        } else {
            if (active) g_Cv[chunk * 224 + n * 16 + c] = S.Ubuf[b][c * 16 + n];
        }
        __threadfence(); __syncthreads();
        if (tid == 0) atomicAdd(&g_cntc[side * SUPER + (chunk >> 4)], 1);

    } else if (bid < BID_SCAN) {
        // ======== supernode role ========
        ChunkS& S = sm.c;
        int idx = bid - BID_SUP;
        int side = (idx < SUPER) ? 0 : 1;
        int s = (side == 0) ? idx : idx - SUPER;
        if (tid == 0) {
            while (atomicAdd(&g_cntc[side * SUPER + s], 0) < SCH) __nanosleep(64);
        }
        __syncthreads(); __threadfence();
        int active = (tid < 196);
        int n = tid % T, c = tid / T;
        if (active)
            S.Ubuf[0][c * 16 + n] = side ? ((n == c) ? 1.0f : 0.0f)
                                         : ((n == c) ? 0.0f : NINF);
        float o = 0.0f; int b = 0;
        __syncthreads();
        for (int k = 0; k < SCH; k++) {
            int ch = s * SCH + k;
            {   const float4* src = (const float4*)(side ? (g_Em + ch * 224)
                                                         : (g_Cv + ch * 224));
                float4* dst = (float4*)S.Etr;
                for (int i = tid; i < 56; i += 256) dst[i] = __ldcg(src + i); }
            float mk = (active && side) ? __ldcg(g_m + ch * 16 + n) : 0.0f;
            __syncthreads();
            if (side) {
                if (active) {
                    float u[T], row[T];
                    ld14(&S.Ubuf[b][c * 16], u);
                    ld14(&S.Etr[n * 16], row);
                    float s0 = 0.0f, s1 = 0.0f;
#pragma unroll
                    for (int p = 0; p < 7; p++) s0 = fmaf(row[p], u[p], s0);
#pragma unroll
                    for (int p = 7; p < T; p++) s1 = fmaf(row[p], u[p], s1);
                    S.Msm[c * 16 + n] = mk + __logf(fmaxf(s0 + s1, 1e-38f));
                }
                __syncthreads();
                if (active) {
                    float tc[T]; ld14(&S.Msm[c * 16], tc);
                    float cmax = max14(tc);
                    S.Ubuf[b ^ 1][c * 16 + n] = __expf(S.Msm[c * 16 + n] - cmax);
                    if (n == 0) o += cmax;
                }
                __syncthreads();
            } else {
                if (active) {
                    float u[T], row[T];
                    ld14(&S.Ubuf[b][c * 16], u);
                    ld14(&S.Etr[n * 16], row);
                    float a[T];
#pragma unroll
                    for (int p = 0; p < T; p++) a[p] = row[p] + u[p];
                    S.Ubuf[b ^ 1][c * 16 + n] = max14(a);
                }
                __syncthreads();
            }
            b ^= 1;
        }
        if (active && n == 0) S.o_s[c] = o;
        __syncthreads();
        if (side) {
            if (active) {
                float Vv = S.Ubuf[b][c * 16 + n];
                S.Msm[n * 16 + c] = (Vv > 0.0f) ? __logf(Vv) + S.o_s[c] : NINF;
            }
            __syncthreads();
            if (active) {
                float r[T]; ld14(&S.Msm[n * 16], r);
                float rm = max14(r);
                g_SEm[s * 224 + n * 16 + c] = __expf(S.Msm[n * 16 + c] - rm);
                if (c == 0) g_Sm[s * 16 + n] = rm;
            }
        } else {
            if (active) g_SCv[s * 224 + n * 16 + c] = S.Ubuf[b][c * 16 + n];
        }
        __threadfence(); __syncthreads();
        if (tid == 0) atomicAdd(&g_cnts[side], 1);

    } else {
        // ======== scan role ========
        int side = (bid == BID_SCAN) ? 0 : 1;
        if (tid == 0) {
            while (atomicAdd(&g_cnts[side], 0) < SUPER) __nanosleep(64);
        }
        __syncthreads(); __threadfence();
        int lane = tid;
        if (lane < 16) {
            const unsigned M16 = 0xFFFFu;
            if (side == 0) {
                float v = (lane == START_TAG) ? 0.0f : NEGV;
                float row[T], nrow[T];
                if (lane < T) ld14cg(g_SCv + lane * 16, row);
                else { for (int p = 0; p < T; p++) row[p] = NINF; }
                for (int i = 0; i < SUPER; i++) {
                    g_vsuper[i * 16 + lane] = (lane < T) ? v : NEGV;
                    if (i + 1 < SUPER) {
                        if (lane < T) ld14cg(g_SCv + (i + 1) * 224 + lane * 16, nrow);
                        else { for (int p = 0; p < T; p++) nrow[p] = NINF; }
                    }
                    float nv = -3e38f;
#pragma unroll
                    for (int p = 0; p < T; p++) {
                        float vp = __shfl_sync(M16, v, p, 16);
                        nv = fmaxf(nv, row[p] + vp);
                    }
                    v = (lane < T) ? nv : NEGV;
#pragma unroll
                    for (int p = 0; p < T; p++) row[p] = nrow[p];
                }
            } else {
                float u = (lane == START_TAG) ? 1.0f : 0.0f;
                float O = 0.0f;
                float row[T], nrow[T], mk, nmk;
                if (lane < T) { ld14cg(g_SEm + lane * 16, row); mk = __ldcg(g_Sm + lane); }
                else { for (int p = 0; p < T; p++) row[p] = 0.0f; mk = -3e38f; }
                for (int i = 0; i < SUPER; i++) {
                    if (i + 1 < SUPER) {
                        if (lane < T) { ld14cg(g_SEm + (i + 1) * 224 + lane * 16, nrow);
                                        nmk = __ldcg(g_Sm + (i + 1) * 16 + lane); }
                        else { for (int p = 0; p < T; p++) nrow[p] = 0.0f; nmk = -3e38f; }
                    }
                    float w = 0.0f;
#pragma unroll
                    for (int p = 0; p < T; p++) {
                        float up = __shfl_sync(M16, u, p, 16);
                        w = fmaf(row[p], up, w);
                    }
                    float t = mk + __logf(fmaxf(w, 1e-38f));
                    float M = t;
#pragma unroll
                    for (int d = 8; d; d >>= 1) M = fmaxf(M, __shfl_xor_sync(M16, M, d, 16));
                    u = __expf(t - M);
                    O += M;
#pragma unroll
                    for (int p = 0; p < T; p++) row[p] = nrow[p];
                    mk = nmk;
                }
                float val = (lane < T) ? (((u > 0.0f) ? __logf(u) : NINF) + O +
                                          trans[STOP_TAG * T + lane])
                                       : -3e38f;
                float M2 = val;
#pragma unroll
                for (int d = 8; d; d >>= 1) M2 = fmaxf(M2, __shfl_xor_sync(M16, M2, d, 16));
                float e = __expf(val - M2);
#pragma unroll
                for (int d = 8; d; d >>= 1) e += __shfl_xor_sync(M16, e, d, 16);
                float fwd_score = M2 + __logf(e);
                float gp = 0.0f;
                for (int j = lane; j < NB_F; j += 16) gp += __ldcg(g_goldpart + j);
#pragma unroll
                for (int d = 8; d; d >>= 1) gp += __shfl_xor_sync(M16, gp, d, 16);
                if (lane == 0) out[0] = fwd_score - gp;   // nll
            }
        }
    }
}

// ---------------- K2: fused bp -> carry -> path ------------------------------
__global__ void __launch_bounds__(128) k_tail(const float* __restrict__ trans,
                                              float* __restrict__ out) {
    __shared__ __align__(16) float feat_s[CB * 16];
    __shared__ __align__(16) unsigned char bp_s[CB * T];
    __shared__ __align__(16) unsigned char Fs[CHUNKS * T];
    __shared__ unsigned char comp_s[8 * T];
    __shared__ float term_s[T];
    __shared__ int sgrp[9];
    __shared__ int role;
    int chunk = blockIdx.x, tid = threadIdx.x;
    // reset k_mid's counters for the NEXT replay (all uses are already done)
    if (tid == 0) {
        g_cntF[chunk] = 0;
        if (chunk < 2 * SUPER) g_cntc[chunk] = 0;
        if (chunk < 2) g_cnts[chunk] = 0;
    }
    {   const float4* src = (const float4*)(g_featsP + chunk * CB * 16);
        float4* dst = (float4*)feat_s;
        for (int i = tid; i < CB * 4; i += 128) dst[i] = src[i]; }
    __syncthreads();
    if (tid < T) {
        int lane = tid;
        int sup = chunk >> 4;
        float v = g_vsuper[sup * 16 + lane];
        for (int k = sup * SCH; k < chunk; k++) {
            float row[T]; ld14(g_Cv + k * 224 + lane * 16, row);
            float fvall[T];
#pragma unroll
            for (int p = 0; p < T; p++) fvall[p] = __shfl_sync(0x3FFFu, v, p);
            float nv = NINF;
#pragma unroll
            for (int p = 0; p < T; p++) nv = fmaxf(nv, row[p] + fvall[p]);
            v = nv;
        }
        float tr[T];
#pragma unroll
        for (int p = 0; p < T; p++) tr[p] = trans[lane * T + p];
        float fv = v;
        for (int l = 0; l < CB; l++) {
            float fvall[T];
#pragma unroll
            for (int p = 0; p < T; p++) fvall[p] = __shfl_sync(0x3FFFu, fv, p);
            float a[T];
#pragma unroll
            for (int p = 0; p < T; p++) a[p] = fvall[p] + tr[p];
            float best; int arg;
            amax14(a, best, arg);
            bp_s[l * T + lane] = (unsigned char)arg;
            fv = best + feat_s[l * 16 + lane];
        }
        __syncwarp(0x3FFFu);
        int t = lane;
        for (int l = CB - 1; l >= 0; l--) t = bp_s[l * T + t];
        g_F[chunk * T + lane] = (unsigned char)t;
        if (chunk == CHUNKS - 1) {
            term_s[lane] = fv + trans[STOP_TAG * T + lane];
            __syncwarp(0x3FFFu);
            if (lane == 0) {
                float a2[T];
#pragma unroll
                for (int p = 0; p < T; p++) a2[p] = term_s[p];
                float best; int arg;
                amax14(a2, best, arg);
                g_best_last = arg;
                out[1] = best;                      // path_score
            }
        }
    }
    __threadfence(); __syncthreads();
    if (tid == 0) {
        int old = atomicAdd(&g_cnt_bp, 1);
        role = (old == CHUNKS - 1);
    }
    __syncthreads();
    if (role) {
        __threadfence();
        {   const int4* src = (const int4*)g_F;
            int4* dst = (int4*)Fs;
            for (int i = tid; i < (CHUNKS * T) / 16; i += 128) dst[i] = __ldcg(src + i); }
        __syncthreads();
        if (tid < 8 * T) {
            int g = tid / T, x = tid % T;
            int t = x;
            for (int l = g * 64 + 63; l >= g * 64; l--) t = Fs[l * T + t];
            comp_s[g * T + x] = (unsigned char)t;
        }
        __syncthreads();
        if (tid == 0) {
            int sgv = g_best_last;
            sgrp[8] = sgv;
            for (int g = 7; g >= 0; g--) { sgv = comp_s[g * T + sgv]; sgrp[g] = sgv; }
        }
        __syncthreads();
        if (tid < 8) {
            int g = tid;
            int t = sgrp[g + 1];
            for (int l = g * 64 + 63; l >= g * 64; l--) {
                g_carry[l] = t;
                t = Fs[l * T + t];
            }
        }
        __threadfence(); __syncthreads();
        if (tid == 0) atomicExch(&g_flag, 1);
    } else {
        if (tid == 0) { while (atomicAdd(&g_flag, 0) == 0) __nanosleep(128); }
        __syncthreads();
    }
    __threadfence();
    if (tid == 0) {
        int cc = g_carry[chunk];
        for (int l = CB - 1; l >= 0; l--) {
            out[2 + chunk * CB + l] = (float)cc;
            cc = bp_s[l * T + cc];
        }
    }
}

// ---------------- launch -----------------------------------------------------
extern "C" void kernel_launch(void* const* d_in, const int* in_sizes, int n_in,
                              void* d_out, int out_size) {
    const int*   sent  = (const int*)d_in[0];
    const int*   tags  = (const int*)d_in[1];
    const float* emb   = (const float*)d_in[2];
    const float* W     = (const float*)d_in[3];
    const float* trans = (const float*)d_in[4];
    float* out = (float*)d_out;
    (void)in_sizes; (void)n_in; (void)out_size;

    k_mid<<<GRID_MID, 256>>>(sent, tags, emb, W, trans, out);
    k_tail<<<CHUNKS, 128>>>(trans, out);
}